// round 16
// baseline (speedup 1.0000x reference)
#include <cuda_runtime.h>
#include <cuda_bf16.h>

#define B_   2
#define S_   2048
#define H_   16
#define D_   64
#define HID_ 1024
#define ROT_ 32
#define BS_  (B_*S_)
#define LOG2E 1.44269504088896f

// ---------------------------------------------------------------------------
// Device-global scratch (allocation-free rule)
// ---------------------------------------------------------------------------
__device__ unsigned g_xH[(size_t)BS_*HID_/2], g_xL[(size_t)BS_*HID_/2];
__device__ unsigned g_WqH[HID_*HID_/2], g_WqL[HID_*HID_/2];
__device__ unsigned g_WkH[HID_*HID_/2], g_WkL[HID_*HID_/2];
__device__ unsigned g_WvH[HID_*HID_/2], g_WvL[HID_*HID_/2];
__device__ unsigned g_WoH[HID_*HID_/2], g_WoL[HID_*HID_/2];
__device__ unsigned g_qH[(size_t)B_*H_*S_*D_/2], g_qL[(size_t)B_*H_*S_*D_/2];
__device__ unsigned g_kH[(size_t)B_*H_*S_*D_/2], g_kL[(size_t)B_*H_*S_*D_/2];
__device__ unsigned g_vH[(size_t)B_*H_*S_*D_/2], g_vL[(size_t)B_*H_*S_*D_/2];
__device__ unsigned g_attnH[(size_t)BS_*HID_/2], g_attnL[(size_t)BS_*HID_/2];
__device__ int g_bias_nz;

// ---------------------------------------------------------------------------
// helpers
// ---------------------------------------------------------------------------
__device__ __forceinline__ unsigned pack_bf(__nv_bfloat16 a, __nv_bfloat16 b) {
    __nv_bfloat162 p; p.x = a; p.y = b;
    return *(unsigned*)&p;
}
__device__ __forceinline__ void split2(float x, float y, unsigned& hi, unsigned& lo) {
    __nv_bfloat16 hx = __float2bfloat16(x);
    __nv_bfloat16 hy = __float2bfloat16(y);
    __nv_bfloat16 lx = __float2bfloat16(x - __bfloat162float(hx));
    __nv_bfloat16 ly = __float2bfloat16(y - __bfloat162float(hy));
    hi = pack_bf(hx, hy);
    lo = pack_bf(lx, ly);
}
__device__ __forceinline__ void mma_bf16(float* d, const unsigned* a, const unsigned* b) {
    asm volatile(
        "mma.sync.aligned.m16n8k16.row.col.f32.bf16.bf16.f32 "
        "{%0,%1,%2,%3},{%4,%5,%6,%7},{%8,%9},{%0,%1,%2,%3};"
        : "+f"(d[0]), "+f"(d[1]), "+f"(d[2]), "+f"(d[3])
        : "r"(a[0]), "r"(a[1]), "r"(a[2]), "r"(a[3]), "r"(b[0]), "r"(b[1]));
}
__device__ __forceinline__ void ldsm4(unsigned* r, unsigned addr) {
    asm volatile("ldmatrix.sync.aligned.m8n8.x4.shared.b16 {%0,%1,%2,%3}, [%4];"
        : "=r"(r[0]), "=r"(r[1]), "=r"(r[2]), "=r"(r[3]) : "r"(addr));
}
__device__ __forceinline__ void ldsm4t(unsigned* r, unsigned addr) {
    asm volatile("ldmatrix.sync.aligned.m8n8.x4.trans.shared.b16 {%0,%1,%2,%3}, [%4];"
        : "=r"(r[0]), "=r"(r[1]), "=r"(r[2]), "=r"(r[3]) : "r"(addr));
}
__device__ __forceinline__ void cp16(unsigned saddr, const void* gptr) {
    asm volatile("cp.async.ca.shared.global [%0], [%1], 16;" :: "r"(saddr), "l"(gptr));
}
#define CP_COMMIT() asm volatile("cp.async.commit_group;")
__device__ __forceinline__ float ex2(float x) {
    float r;
    asm("ex2.approx.ftz.f32 %0, %1;" : "=f"(r) : "f"(x));
    return r;
}

// ---------------------------------------------------------------------------
// Prep: one launch.  z=0..3 -> W matrices (1024 blocks); z=4 -> x (4096 blocks)
// ---------------------------------------------------------------------------
__global__ void prep_all(const float* __restrict__ x,
                         const float* __restrict__ Wq, const float* __restrict__ Wk,
                         const float* __restrict__ Wv, const float* __restrict__ Wo) {
    const int z = blockIdx.z;
    if (z == 4) {
        const int i = blockIdx.x * 256 + threadIdx.x;
        if (blockIdx.x == 0 && threadIdx.x == 0) g_bias_nz = 0;
        float4 v = ((const float4*)x)[i];
        uint2 h, l;
        split2(v.x, v.y, h.x, l.x);
        split2(v.z, v.w, h.y, l.y);
        ((uint2*)g_xH)[i] = h;
        ((uint2*)g_xL)[i] = l;
        return;
    }
    if (blockIdx.x >= 1024) return;
    const float* W = z == 0 ? Wq : z == 1 ? Wk : z == 2 ? Wv : Wo;
    unsigned* Hd = z == 0 ? g_WqH : z == 1 ? g_WkH : z == 2 ? g_WvH : g_WoH;
    unsigned* Ld = z == 0 ? g_WqL : z == 1 ? g_WkL : z == 2 ? g_WvL : g_WoL;
    const int j  = blockIdx.x * 256 + threadIdx.x;
    const int k  = j >> 8;
    const int n4 = (j & 255) * 4;
    float4 a = *(const float4*)&W[(size_t)k * HID_ + n4];
    uint2 h, l;
    split2(a.x, a.y, h.x, l.x);
    split2(a.z, a.w, h.y, l.y);
    *(uint2*)&Hd[(size_t)k * 512 + (n4 >> 1)] = h;
    *(uint2*)&Ld[(size_t)k * 512 + (n4 >> 1)] = l;
}

__global__ void bias_check(const float* __restrict__ b) {
    const size_t i = (size_t)blockIdx.x * 256 + threadIdx.x;
    float4 v = ((const float4*)b)[i];
    if (v.x != 0.0f || v.y != 0.0f || v.z != 0.0f || v.w != 0.0f) g_bias_nz = 1;
}

// ---------------------------------------------------------------------------
// GEMM smem: BK=64 (32 kwords/stage), 2-stage.  A [2][128][36]; B [2][64][68].
// Word offsets:
// ---------------------------------------------------------------------------
#define ASH_OFF 0
#define ASL_OFF 9216
#define BSH_OFF 18432
#define BSL_OFF 27136
#define GEMM_SMEM_BYTES (35840 * 4)    // 143360

__device__ __forceinline__ void gemm_ld_stage(
    unsigned smemBase, int s, int tid, int bm, int n0w, int it,
    const unsigned* __restrict__ AH, const unsigned* __restrict__ AL,
    const unsigned* __restrict__ WH, const unsigned* __restrict__ WL)
{
    const int ktw   = it * 32;        // word offset in A rows
    const int kbase = it * 64;        // k-row offset in B
    const int w4  = (tid & 7) * 4;
    const int w4b = (tid & 15) * 4;
    #pragma unroll
    for (int p = 0; p < 4; p++) {
        const int rowA = (tid >> 3) + p * 32;
        const size_t ga = (size_t)(bm + rowA) * 512 + ktw + w4;
        cp16(smemBase + (ASH_OFF + s * 4608 + rowA * 36 + w4) * 4, &AH[ga]);
        cp16(smemBase + (ASL_OFF + s * 4608 + rowA * 36 + w4) * 4, &AL[ga]);
        const int rowB = (tid >> 4) + p * 16;
        const size_t gb = (size_t)(kbase + rowB) * 512 + n0w + w4b;
        cp16(smemBase + (BSH_OFF + s * 4352 + rowB * 68 + w4b) * 4, &WH[gb]);
        cp16(smemBase + (BSL_OFF + s * 4352 + rowB * 68 + w4b) * 4, &WL[gb]);
    }
}

// 2-stage, BK=64, ONE __syncthreads per iteration (16 iters).
// Load for it+1 targets slot buf^1 (consumed at it-1) and is issued after
// sync(it), when every thread has finished compute(it-1).
#define GEMM_MAINLOOP(AHsrc, ALsrc, WHsrc, WLsrc, N0W)                                  \
    gemm_ld_stage(smemBase, 0, tid, bm, N0W, 0, AHsrc, ALsrc, WHsrc, WLsrc);            \
    CP_COMMIT();                                                                        \
    for (int it = 0; it < 16; it++) {                                                   \
        const int buf = it & 1;                                                         \
        asm volatile("cp.async.wait_group 0;");                                         \
        __syncthreads();                                                                \
        if (it + 1 < 16) {                                                              \
            gemm_ld_stage(smemBase, buf ^ 1, tid, bm, N0W, it + 1,                      \
                          AHsrc, ALsrc, WHsrc, WLsrc);                                  \
            CP_COMMIT();                                                                \
        }                                                                               \
        _Pragma("unroll")                                                               \
        for (int ks = 0; ks < 4; ks++) {                                                \
            unsigned aH[4][4], aL[4][4], bH[4][2], bL[4][2];                            \
            const int arow = wm * 64 + (lane & 15);                                     \
            const int acol = ks * 8 + (lane >> 4) * 4;                                  \
            _Pragma("unroll")                                                           \
            for (int mt = 0; mt < 4; mt++) {                                            \
                ldsm4(aH[mt], smemBase + (ASH_OFF + buf * 4608 +                        \
                       (arow + mt * 16) * 36 + acol) * 4);                              \
                ldsm4(aL[mt], smemBase + (ASL_OFF + buf * 4608 +                        \
                       (arow + mt * 16) * 36 + acol) * 4);                              \
            }                                                                           \
            const int bkr = ks * 16 + (lane & 15);                                      \
            const int bnc = wn * 16 + (lane >> 4) * 4;                                  \
            _Pragma("unroll")                                                           \
            for (int np = 0; np < 2; np++) {                                            \
                unsigned r[4];                                                          \
                ldsm4t(r, smemBase + (BSH_OFF + buf * 4352 + bkr * 68 + bnc + np * 8) * 4); \
                bH[2*np][0] = r[0]; bH[2*np][1] = r[1];                                 \
                bH[2*np+1][0] = r[2]; bH[2*np+1][1] = r[3];                             \
                ldsm4t(r, smemBase + (BSL_OFF + buf * 4352 + bkr * 68 + bnc + np * 8) * 4); \
                bL[2*np][0] = r[0]; bL[2*np][1] = r[1];                                 \
                bL[2*np+1][0] = r[2]; bL[2*np+1][1] = r[3];                             \
            }                                                                           \
            _Pragma("unroll")                                                           \
            for (int mt = 0; mt < 4; mt++)                                              \
                _Pragma("unroll")                                                       \
                for (int nt = 0; nt < 4; nt++) {                                        \
                    mma_bf16(acc[mt][nt], aH[mt], bH[nt]);                              \
                    mma_bf16(acc[mt][nt], aH[mt], bL[nt]);                              \
                    mma_bf16(acc[mt][nt], aL[mt], bH[nt]);                              \
                }                                                                       \
        }                                                                               \
    }

// ---------------------------------------------------------------------------
// Kernel 1: fused QKV GEMM.  q/k/v ALL written pre-packed bf16 hi/lo.
// ---------------------------------------------------------------------------
__global__ __launch_bounds__(256) void qkv_kernel(
    const float* __restrict__ sinu,
    const float* __restrict__ bq, const float* __restrict__ bk,
    const float* __restrict__ bv)
{
    extern __shared__ unsigned sm[];
    const unsigned smemBase = (unsigned)__cvta_generic_to_shared(sm);

    const int bn  = blockIdx.x * 128;
    const int bm  = blockIdx.y * 128;
    const int mat = bn >> 10;
    const unsigned* __restrict__ WH = mat == 0 ? g_WqH : mat == 1 ? g_WkH : g_WvH;
    const unsigned* __restrict__ WL = mat == 0 ? g_WqL : mat == 1 ? g_WkL : g_WvL;
    const float*    __restrict__ bvec = mat == 0 ? bq : mat == 1 ? bk : bv;
    const int n0w = (bn & (HID_ - 1)) >> 1;

    const int tid  = threadIdx.x;
    const int lane = tid & 31;
    const int g    = lane >> 2;
    const int t    = lane & 3;
    const int wm   = (tid >> 5) >> 2;
    const int wn   = (tid >> 5) & 3;

    float acc[4][4][4];
    #pragma unroll
    for (int i = 0; i < 4; i++)
        #pragma unroll
        for (int j = 0; j < 4; j++)
            #pragma unroll
            for (int e = 0; e < 4; e++) acc[i][j][e] = 0.0f;

    GEMM_MAINLOOP(g_xH, g_xL, WH, WL, n0w)

    unsigned* __restrict__ dH = mat == 0 ? g_qH : mat == 1 ? g_kH : g_vH;
    unsigned* __restrict__ dL = mat == 0 ? g_qL : mat == 1 ? g_kL : g_vL;

    #pragma unroll
    for (int mt = 0; mt < 4; mt++) {
        #pragma unroll
        for (int nt = 0; nt < 4; nt++) {
            const int colg = bn + wn * 32 + nt * 8 + t * 2;
            const int cm   = colg & (HID_ - 1);
            const int hh   = cm >> 6;
            const int d0   = cm & 63;
            #pragma unroll
            for (int half = 0; half < 2; half++) {
                const int row  = bm + wm * 64 + mt * 16 + g + half * 8;
                const int bidx = row >> 11;
                const int s    = row & (S_ - 1);
                float v0 = acc[mt][nt][half * 2 + 0] + bvec[cm];
                float v1 = acc[mt][nt][half * 2 + 1] + bvec[cm + 1];
                if (mat < 2 && d0 < ROT_) {
                    const float sn0 = sinu[(((bidx * 2 + 0) * S_ + s) << 5) + d0];
                    const float cs0 = sinu[(((bidx * 2 + 1) * S_ + s) << 5) + d0];
                    const float sn1 = sinu[(((bidx * 2 + 0) * S_ + s) << 5) + d0 + 1];
                    const float cs1 = sinu[(((bidx * 2 + 1) * S_ + s) << 5) + d0 + 1];
                    v0 *= (cs0 - sn0);
                    v1 *= (cs1 + sn1);
                }
                if (mat == 0) { v0 *= 0.125f * LOG2E; v1 *= 0.125f * LOG2E; }
                const size_t base = ((size_t)bidx * H_ + hh) * S_ + s;
                unsigned hw, lw;
                split2(v0, v1, hw, lw);
                dH[base * 32 + (d0 >> 1)] = hw;
                dL[base * 32 + (d0 >> 1)] = lw;
            }
        }
    }
}

// ---------------------------------------------------------------------------
// Kernel 2: flash attention (round-15 winner, unchanged).
// ---------------------------------------------------------------------------
#define A_KSH 0              // [3][64][36]
#define A_KSL 6912
#define A_VSH 13824          // [3][64][36]
#define A_VSL 20736
#define A_PSH 27648          // [128][36]
#define ATTN_SMEM_BYTES (32256 * 4)   // 129024

#define S_GEMM(dst, bufidx)                                                     \
    _Pragma("unroll")                                                           \
    for (int nt = 0; nt < 8; nt++)                                              \
        _Pragma("unroll")                                                       \
        for (int e = 0; e < 4; e++) dst[nt][e] = 0.0f;                          \
    _Pragma("unroll")                                                           \
    for (int w = 0; w < 4; w++) {                                               \
        _Pragma("unroll")                                                       \
        for (int np = 0; np < 4; np++) {                                        \
            unsigned rH[4], rL[4];                                              \
            const unsigned off = (A_KSH + (bufidx) * 2304 +                     \
                 (np * 16 + kfr) * 36 + w * 8 + kfd) * 4;                       \
            ldsm4(rH, smemBase + off);                                          \
            ldsm4(rL, smemBase + off + (A_KSL - A_KSH) * 4);                    \
            mma_bf16(dst[2*np],   qaH[w], rH);                                  \
            mma_bf16(dst[2*np],   qaH[w], rL);                                  \
            mma_bf16(dst[2*np],   qaL[w], rH);                                  \
            mma_bf16(dst[2*np+1], qaH[w], rH + 2);                              \
            mma_bf16(dst[2*np+1], qaH[w], rL + 2);                              \
            mma_bf16(dst[2*np+1], qaL[w], rH + 2);                              \
        }                                                                       \
    }

#define PV_GEMM(w0, w1, bufidx)                                                 \
    _Pragma("unroll")                                                           \
    for (int w = (w0); w < (w1); w++) {                                         \
        unsigned paH[4];                                                        \
        ldsm4(paH, smemBase + (A_PSH + pfr * 36 + w * 8 + pfc) * 4);            \
        _Pragma("unroll")                                                       \
        for (int np = 0; np < 4; np++) {                                        \
            unsigned rH[4], rL[4];                                              \
            const unsigned off = (A_VSH + (bufidx) * 2304 +                     \
                 (w * 16 + vfr) * 36 + np * 8 + vfc) * 4;                       \
            ldsm4t(rH, smemBase + off);                                         \
            ldsm4t(rL, smemBase + off + (A_VSL - A_VSH) * 4);                   \
            mma_bf16(oacc[2*np],   paH, rH);                                    \
            mma_bf16(oacc[2*np],   paH, rL);                                    \
            mma_bf16(oacc[2*np+1], paH, rH + 2);                                \
            mma_bf16(oacc[2*np+1], paH, rL + 2);                                \
        }                                                                       \
    }

__global__ __launch_bounds__(256) void attn_kernel(const float* __restrict__ bias)
{
    extern __shared__ unsigned sm[];
    const unsigned smemBase = (unsigned)__cvta_generic_to_shared(sm);

    const int bidx = blockIdx.z;
    const int h    = blockIdx.y;
    const int q0   = blockIdx.x * 128;
    const int tid  = threadIdx.x;
    const int lane = tid & 31;
    const int g    = lane >> 2;
    const int t    = lane & 3;
    const int rb   = (tid >> 5) * 16;

    const int has_bias = g_bias_nz;

    const size_t bh = (size_t)bidx * H_ + h;
    const unsigned* __restrict__ qHp = g_qH + (bh * S_ + q0) * 32;
    const unsigned* __restrict__ qLp = g_qL + (bh * S_ + q0) * 32;
    const unsigned* __restrict__ kHp = g_kH + bh * S_ * 32;
    const unsigned* __restrict__ kLp = g_kL + bh * S_ * 32;
    const unsigned* __restrict__ vHp = g_vH + bh * S_ * 32;
    const unsigned* __restrict__ vLp = g_vL + bh * S_ * 32;

    unsigned qaH[4][4], qaL[4][4];
    #pragma unroll
    for (int w = 0; w < 4; w++) {
        qaH[w][0] = qHp[(rb + g)     * 32 + w * 8 + t];
        qaH[w][1] = qHp[(rb + 8 + g) * 32 + w * 8 + t];
        qaH[w][2] = qHp[(rb + g)     * 32 + w * 8 + t + 4];
        qaH[w][3] = qHp[(rb + 8 + g) * 32 + w * 8 + t + 4];
        qaL[w][0] = qLp[(rb + g)     * 32 + w * 8 + t];
        qaL[w][1] = qLp[(rb + 8 + g) * 32 + w * 8 + t];
        qaL[w][2] = qLp[(rb + g)     * 32 + w * 8 + t + 4];
        qaL[w][3] = qLp[(rb + 8 + g) * 32 + w * 8 + t + 4];
    }

    float oacc[8][4];
    #pragma unroll
    for (int i = 0; i < 8; i++)
        #pragma unroll
        for (int e = 0; e < 4; e++) oacc[i][e] = 0.0f;
    float m0 = -1e30f, m1 = -1e30f, l0 = 0.0f, l1 = 0.0f;

    const int krow = tid >> 3, kw4 = (tid & 7) * 4;

    const int kfr = (lane & 7) + ((lane >> 4) & 1) * 8;
    const int kfd = ((lane >> 3) & 1) * 4;
    const int vfr = (lane & 7) + ((lane >> 3) & 1) * 8;
    const int vfc = (lane >> 4) * 4;
    const int pfr = rb + (lane & 15);
    const int pfc = (lane >> 4) * 4;

    #pragma unroll
    for (int s = 0; s < 2; s++) {
        #pragma unroll
        for (int p = 0; p < 2; p++) {
            const int r = krow + p * 32;
            const size_t gr = (size_t)(s * 64 + r) * 32 + kw4;
            cp16(smemBase + (A_KSH + s * 2304 + r * 36 + kw4) * 4, &kHp[gr]);
            cp16(smemBase + (A_KSL + s * 2304 + r * 36 + kw4) * 4, &kLp[gr]);
            cp16(smemBase + (A_VSH + s * 2304 + r * 36 + kw4) * 4, &vHp[gr]);
            cp16(smemBase + (A_VSL + s * 2304 + r * 36 + kw4) * 4, &vLp[gr]);
        }
        CP_COMMIT();
    }
    asm volatile("cp.async.wait_group 1;");
    __syncthreads();

    const size_t brow0 = ((size_t)bidx * S_ + (q0 + rb + g)) * S_;
    const size_t brow1 = brow0 + (size_t)8 * S_;

    float scur[8][4], snxt[8][4];
    S_GEMM(scur, 0)

    int bc = 0;
    for (int c = 0; c < 32; c++) {
        const int bnx = (bc == 2) ? 0 : bc + 1;
        const int bpl = (bnx == 2) ? 0 : bnx + 1;

        asm volatile("cp.async.wait_group 0;");
        __syncthreads();

        if (c + 2 < 32) {
            const int kt2 = (c + 2) * 64;
            #pragma unroll
            for (int p = 0; p < 2; p++) {
                const int r = krow + p * 32;
                const size_t gr = (size_t)(kt2 + r) * 32 + kw4;
                cp16(smemBase + (A_KSH + bpl * 2304 + r * 36 + kw4) * 4, &kHp[gr]);
                cp16(smemBase + (A_KSL + bpl * 2304 + r * 36 + kw4) * 4, &kLp[gr]);
                cp16(smemBase + (A_VSH + bpl * 2304 + r * 36 + kw4) * 4, &vHp[gr]);
                cp16(smemBase + (A_VSL + bpl * 2304 + r * 36 + kw4) * 4, &vLp[gr]);
            }
            CP_COMMIT();
        }

        float2 bb0[8], bb1[8];
        if (has_bias) {
            #pragma unroll
            for (int nt = 0; nt < 8; nt++) {
                bb0[nt] = *(const float2*)&bias[brow0 + c * 64 + nt * 8 + t * 2];
                bb1[nt] = *(const float2*)&bias[brow1 + c * 64 + nt * 8 + t * 2];
            }
        }

        if (c + 1 < 32) {
            S_GEMM(snxt, bnx)
        }

        if (has_bias) {
            #pragma unroll
            for (int nt = 0; nt < 8; nt++) {
                scur[nt][0] += LOG2E * bb0[nt].x; scur[nt][1] += LOG2E * bb0[nt].y;
                scur[nt][2] += LOG2E * bb1[nt].x; scur[nt][3] += LOG2E * bb1[nt].y;
            }
        }

        float mx0 = -1e30f, mx1 = -1e30f;
        #pragma unroll
        for (int nt = 0; nt < 8; nt++) {
            mx0 = fmaxf(mx0, fmaxf(scur[nt][0], scur[nt][1]));
            mx1 = fmaxf(mx1, fmaxf(scur[nt][2], scur[nt][3]));
        }
        mx0 = fmaxf(mx0, __shfl_xor_sync(0xffffffffu, mx0, 1));
        mx0 = fmaxf(mx0, __shfl_xor_sync(0xffffffffu, mx0, 2));
        mx1 = fmaxf(mx1, __shfl_xor_sync(0xffffffffu, mx1, 1));
        mx1 = fmaxf(mx1, __shfl_xor_sync(0xffffffffu, mx1, 2));
        const float mi0 = fmaxf(m0, mx0), mi1 = fmaxf(m1, mx1);
        const float c0 = ex2(m0 - mi0), c1 = ex2(m1 - mi1);
        m0 = mi0; m1 = mi1;
        #pragma unroll
        for (int nt = 0; nt < 8; nt++) {
            oacc[nt][0] *= c0; oacc[nt][1] *= c0;
            oacc[nt][2] *= c1; oacc[nt][3] *= c1;
        }

        float rs0 = 0.0f, rs1 = 0.0f;
        #pragma unroll
        for (int nt = 0; nt < 4; nt++) {
            scur[nt][0] = ex2(scur[nt][0] - mi0);
            scur[nt][1] = ex2(scur[nt][1] - mi0);
            scur[nt][2] = ex2(scur[nt][2] - mi1);
            scur[nt][3] = ex2(scur[nt][3] - mi1);
            rs0 += scur[nt][0] + scur[nt][1];
            rs1 += scur[nt][2] + scur[nt][3];
            sm[A_PSH + (rb + g) * 36 + nt * 4 + t] =
                pack_bf(__float2bfloat16(scur[nt][0]), __float2bfloat16(scur[nt][1]));
            sm[A_PSH + (rb + 8 + g) * 36 + nt * 4 + t] =
                pack_bf(__float2bfloat16(scur[nt][2]), __float2bfloat16(scur[nt][3]));
        }
        __syncwarp();
        PV_GEMM(0, 2, bc)

        #pragma unroll
        for (int nt = 4; nt < 8; nt++) {
            scur[nt][0] = ex2(scur[nt][0] - mi0);
            scur[nt][1] = ex2(scur[nt][1] - mi0);
            scur[nt][2] = ex2(scur[nt][2] - mi1);
            scur[nt][3] = ex2(scur[nt][3] - mi1);
            rs0 += scur[nt][0] + scur[nt][1];
            rs1 += scur[nt][2] + scur[nt][3];
            sm[A_PSH + (rb + g) * 36 + nt * 4 + t] =
                pack_bf(__float2bfloat16(scur[nt][0]), __float2bfloat16(scur[nt][1]));
            sm[A_PSH + (rb + 8 + g) * 36 + nt * 4 + t] =
                pack_bf(__float2bfloat16(scur[nt][2]), __float2bfloat16(scur[nt][3]));
        }
        __syncwarp();
        PV_GEMM(2, 4, bc)

        rs0 += __shfl_xor_sync(0xffffffffu, rs0, 1);
        rs0 += __shfl_xor_sync(0xffffffffu, rs0, 2);
        rs1 += __shfl_xor_sync(0xffffffffu, rs1, 1);
        rs1 += __shfl_xor_sync(0xffffffffu, rs1, 2);
        l0 = l0 * c0 + rs0;
        l1 = l1 * c1 + rs1;

        if (c + 1 < 32) {
            #pragma unroll
            for (int nt = 0; nt < 8; nt++)
                #pragma unroll
                for (int e = 0; e < 4; e++) scur[nt][e] = snxt[nt][e];
        }
        bc = bnx;
    }

    const float inv0 = 1.0f / l0, inv1 = 1.0f / l1;
    #pragma unroll
    for (int nt = 0; nt < 8; nt++) {
        const int col = h * D_ + nt * 8 + t * 2;
        const int r0  = q0 + rb + g;
        unsigned hw, lw;
        split2(oacc[nt][0] * inv0, oacc[nt][1] * inv0, hw, lw);
        g_attnH[((size_t)(bidx * S_ + r0)) * 512 + (col >> 1)] = hw;
        g_attnL[((size_t)(bidx * S_ + r0)) * 512 + (col >> 1)] = lw;
        split2(oacc[nt][2] * inv1, oacc[nt][3] * inv1, hw, lw);
        g_attnH[((size_t)(bidx * S_ + r0 + 8)) * 512 + (col >> 1)] = hw;
        g_attnL[((size_t)(bidx * S_ + r0 + 8)) * 512 + (col >> 1)] = lw;
    }
}

// ---------------------------------------------------------------------------
// Kernel 3: output projection
// ---------------------------------------------------------------------------
__global__ __launch_bounds__(256) void proj_kernel(float* __restrict__ out)
{
    extern __shared__ unsigned sm[];
    const unsigned smemBase = (unsigned)__cvta_generic_to_shared(sm);

    const int bn = blockIdx.x * 128;
    const int bm = blockIdx.y * 128;
    const int n0w = bn >> 1;

    const int tid  = threadIdx.x;
    const int lane = tid & 31;
    const int g    = lane >> 2;
    const int t    = lane & 3;
    const int wm   = (tid >> 5) >> 2;
    const int wn   = (tid >> 5) & 3;

    float acc[4][4][4];
    #pragma unroll
    for (int i = 0; i < 4; i++)
        #pragma unroll
        for (int j = 0; j < 4; j++)
            #pragma unroll
            for (int e = 0; e < 4; e++) acc[i][j][e] = 0.0f;

    GEMM_MAINLOOP(g_attnH, g_attnL, g_WoH, g_WoL, n0w)

    #pragma unroll
    for (int mt = 0; mt < 4; mt++) {
        #pragma unroll
        for (int nt = 0; nt < 4; nt++) {
            const int col = bn + wn * 32 + nt * 8 + t * 2;
            #pragma unroll
            for (int half = 0; half < 2; half++) {
                const int row = bm + wm * 64 + mt * 16 + g + half * 8;
                float2 o = make_float2(acc[mt][nt][half * 2], acc[mt][nt][half * 2 + 1]);
                *(float2*)&out[(size_t)row * HID_ + col] = o;
            }
        }
    }
}

// ---------------------------------------------------------------------------
extern "C" void kernel_launch(void* const* d_in, const int* in_sizes, int n_in,
                              void* d_out, int out_size)
{
    const float* x    = (const float*)d_in[0];
    const float* sinu = (const float*)d_in[1];
    const float* bias = (const float*)d_in[2];
    const float* Wq   = (const float*)d_in[3];
    const float* bq   = (const float*)d_in[4];
    const float* Wk   = (const float*)d_in[5];
    const float* bk   = (const float*)d_in[6];
    const float* Wv   = (const float*)d_in[7];
    const float* bv   = (const float*)d_in[8];
    const float* Wo   = (const float*)d_in[9];
    float* out = (float*)d_out;

    cudaFuncSetAttribute(qkv_kernel,  cudaFuncAttributeMaxDynamicSharedMemorySize, GEMM_SMEM_BYTES);
    cudaFuncSetAttribute(attn_kernel, cudaFuncAttributeMaxDynamicSharedMemorySize, ATTN_SMEM_BYTES);
    cudaFuncSetAttribute(proj_kernel, cudaFuncAttributeMaxDynamicSharedMemorySize, GEMM_SMEM_BYTES);

    prep_all<<<dim3(4096, 1, 5), 256>>>(x, Wq, Wk, Wv, Wo);
    bias_check<<<(size_t)B_ * S_ * S_ / 4 / 256, 256>>>(bias);

    qkv_kernel<<<dim3(24, 32), 256, GEMM_SMEM_BYTES>>>(sinu, bq, bk, bv);
    attn_kernel<<<dim3(S_ / 128, H_, B_), 256, ATTN_SMEM_BYTES>>>(bias);
    proj_kernel<<<dim3(8, 32), 256, GEMM_SMEM_BYTES>>>(out);
}

// round 17
// speedup vs baseline: 1.4780x; 1.4780x over previous
#include <cuda_runtime.h>
#include <cuda_bf16.h>

#define B_   2
#define S_   2048
#define H_   16
#define D_   64
#define HID_ 1024
#define ROT_ 32
#define BS_  (B_*S_)
#define LOG2E 1.44269504088896f

// ---------------------------------------------------------------------------
// Device-global scratch (allocation-free rule)
// ---------------------------------------------------------------------------
__device__ unsigned g_xH[(size_t)BS_*HID_/2], g_xL[(size_t)BS_*HID_/2];
__device__ unsigned g_WqH[HID_*HID_/2], g_WqL[HID_*HID_/2];
__device__ unsigned g_WkH[HID_*HID_/2], g_WkL[HID_*HID_/2];
__device__ unsigned g_WvH[HID_*HID_/2], g_WvL[HID_*HID_/2];
__device__ unsigned g_WoH[HID_*HID_/2], g_WoL[HID_*HID_/2];
__device__ unsigned g_qH[(size_t)B_*H_*S_*D_/2], g_qL[(size_t)B_*H_*S_*D_/2];
__device__ unsigned g_kH[(size_t)B_*H_*S_*D_/2], g_kL[(size_t)B_*H_*S_*D_/2];
__device__ unsigned g_vH[(size_t)B_*H_*S_*D_/2], g_vL[(size_t)B_*H_*S_*D_/2];
__device__ unsigned g_attnH[(size_t)BS_*HID_/2], g_attnL[(size_t)BS_*HID_/2];
__device__ int g_bias_nz;

// ---------------------------------------------------------------------------
// helpers
// ---------------------------------------------------------------------------
__device__ __forceinline__ unsigned pack_bf(__nv_bfloat16 a, __nv_bfloat16 b) {
    __nv_bfloat162 p; p.x = a; p.y = b;
    return *(unsigned*)&p;
}
__device__ __forceinline__ void split2(float x, float y, unsigned& hi, unsigned& lo) {
    __nv_bfloat16 hx = __float2bfloat16(x);
    __nv_bfloat16 hy = __float2bfloat16(y);
    __nv_bfloat16 lx = __float2bfloat16(x - __bfloat162float(hx));
    __nv_bfloat16 ly = __float2bfloat16(y - __bfloat162float(hy));
    hi = pack_bf(hx, hy);
    lo = pack_bf(lx, ly);
}
__device__ __forceinline__ void mma_bf16(float* d, const unsigned* a, const unsigned* b) {
    asm volatile(
        "mma.sync.aligned.m16n8k16.row.col.f32.bf16.bf16.f32 "
        "{%0,%1,%2,%3},{%4,%5,%6,%7},{%8,%9},{%0,%1,%2,%3};"
        : "+f"(d[0]), "+f"(d[1]), "+f"(d[2]), "+f"(d[3])
        : "r"(a[0]), "r"(a[1]), "r"(a[2]), "r"(a[3]), "r"(b[0]), "r"(b[1]));
}
__device__ __forceinline__ void ldsm4(unsigned* r, unsigned addr) {
    asm volatile("ldmatrix.sync.aligned.m8n8.x4.shared.b16 {%0,%1,%2,%3}, [%4];"
        : "=r"(r[0]), "=r"(r[1]), "=r"(r[2]), "=r"(r[3]) : "r"(addr));
}
__device__ __forceinline__ void ldsm4t(unsigned* r, unsigned addr) {
    asm volatile("ldmatrix.sync.aligned.m8n8.x4.trans.shared.b16 {%0,%1,%2,%3}, [%4];"
        : "=r"(r[0]), "=r"(r[1]), "=r"(r[2]), "=r"(r[3]) : "r"(addr));
}
__device__ __forceinline__ void cp16(unsigned saddr, const void* gptr) {
    asm volatile("cp.async.ca.shared.global [%0], [%1], 16;" :: "r"(saddr), "l"(gptr));
}
#define CP_COMMIT() asm volatile("cp.async.commit_group;")
__device__ __forceinline__ float ex2(float x) {
    float r;
    asm("ex2.approx.ftz.f32 %0, %1;" : "=f"(r) : "f"(x));
    return r;
}

// ---------------------------------------------------------------------------
// Prep: one launch.  z=0..3 -> W matrices (1024 blocks); z=4 -> x (4096 blocks)
// ---------------------------------------------------------------------------
__global__ void prep_all(const float* __restrict__ x,
                         const float* __restrict__ Wq, const float* __restrict__ Wk,
                         const float* __restrict__ Wv, const float* __restrict__ Wo) {
    const int z = blockIdx.z;
    if (z == 4) {
        const int i = blockIdx.x * 256 + threadIdx.x;
        if (blockIdx.x == 0 && threadIdx.x == 0) g_bias_nz = 0;
        float4 v = ((const float4*)x)[i];
        uint2 h, l;
        split2(v.x, v.y, h.x, l.x);
        split2(v.z, v.w, h.y, l.y);
        ((uint2*)g_xH)[i] = h;
        ((uint2*)g_xL)[i] = l;
        return;
    }
    if (blockIdx.x >= 1024) return;
    const float* W = z == 0 ? Wq : z == 1 ? Wk : z == 2 ? Wv : Wo;
    unsigned* Hd = z == 0 ? g_WqH : z == 1 ? g_WkH : z == 2 ? g_WvH : g_WoH;
    unsigned* Ld = z == 0 ? g_WqL : z == 1 ? g_WkL : z == 2 ? g_WvL : g_WoL;
    const int j  = blockIdx.x * 256 + threadIdx.x;
    const int k  = j >> 8;
    const int n4 = (j & 255) * 4;
    float4 a = *(const float4*)&W[(size_t)k * HID_ + n4];
    uint2 h, l;
    split2(a.x, a.y, h.x, l.x);
    split2(a.z, a.w, h.y, l.y);
    *(uint2*)&Hd[(size_t)k * 512 + (n4 >> 1)] = h;
    *(uint2*)&Ld[(size_t)k * 512 + (n4 >> 1)] = l;
}

__global__ void bias_check(const float* __restrict__ b) {
    const size_t i = (size_t)blockIdx.x * 256 + threadIdx.x;
    float4 v = ((const float4*)b)[i];
    if (v.x != 0.0f || v.y != 0.0f || v.z != 0.0f || v.w != 0.0f) g_bias_nz = 1;
}

// ---------------------------------------------------------------------------
// GEMM smem: 3-stage ring.  A [3][128][20] H+L; B [3][32][68] H+L (words).
// ---------------------------------------------------------------------------
#define ASH_OFF 0
#define ASL_OFF 7680
#define BSH_OFF 15360
#define BSL_OFF 21888
#define GEMM_SMEM_BYTES (28416 * 4)    // 113664

__device__ __forceinline__ void gemm_ld_stage(
    unsigned smemBase, int s, int tid, int bm, int n0w, int ktw,
    const unsigned* __restrict__ AH, const unsigned* __restrict__ AL,
    const unsigned* __restrict__ WH, const unsigned* __restrict__ WL)
{
    #pragma unroll
    for (int p = 0; p < 2; p++) {
        const int c   = tid + p * 256;
        const int row = c >> 2;
        const int w4  = (c & 3) * 4;
        const size_t ga = (size_t)(bm + row) * 512 + ktw + w4;
        cp16(smemBase + (ASH_OFF + s * 2560 + row * 20 + w4) * 4, &AH[ga]);
        cp16(smemBase + (ASL_OFF + s * 2560 + row * 20 + w4) * 4, &AL[ga]);
        const int krow = c >> 4;
        const int w4b  = (c & 15) * 4;
        const size_t gb = (size_t)(2 * ktw + krow) * 512 + n0w + w4b;
        cp16(smemBase + (BSH_OFF + s * 2176 + krow * 68 + w4b) * 4, &WH[gb]);
        cp16(smemBase + (BSL_OFF + s * 2176 + krow * 68 + w4b) * 4, &WL[gb]);
    }
}

#define GEMM_MAINLOOP(AHsrc, ALsrc, WHsrc, WLsrc, N0W)                                  \
    gemm_ld_stage(smemBase, 0, tid, bm, N0W, 0,  AHsrc, ALsrc, WHsrc, WLsrc);           \
    CP_COMMIT();                                                                        \
    gemm_ld_stage(smemBase, 1, tid, bm, N0W, 16, AHsrc, ALsrc, WHsrc, WLsrc);           \
    CP_COMMIT();                                                                        \
    for (int it = 0; it < 32; it++) {                                                   \
        const int buf = it % 3;                                                         \
        if (it < 31) asm volatile("cp.async.wait_group 1;");                            \
        else         asm volatile("cp.async.wait_group 0;");                            \
        __syncthreads();                                                                \
        if (it + 2 < 32) {                                                              \
            gemm_ld_stage(smemBase, (it + 2) % 3, tid, bm, N0W, (it + 2) * 16,          \
                          AHsrc, ALsrc, WHsrc, WLsrc);                                  \
            CP_COMMIT();                                                                \
        }                                                                               \
        _Pragma("unroll")                                                               \
        for (int ks = 0; ks < 2; ks++) {                                                \
            unsigned aH[4][4], aL[4][4], bH[4][2], bL[4][2];                            \
            const int arow = wm * 64 + (lane & 15);                                     \
            const int acol = ks * 8 + (lane >> 4) * 4;                                  \
            _Pragma("unroll")                                                           \
            for (int mt = 0; mt < 4; mt++) {                                            \
                ldsm4(aH[mt], smemBase + (ASH_OFF + buf * 2560 +                        \
                       (arow + mt * 16) * 20 + acol) * 4);                              \
                ldsm4(aL[mt], smemBase + (ASL_OFF + buf * 2560 +                        \
                       (arow + mt * 16) * 20 + acol) * 4);                              \
            }                                                                           \
            const int bkr = ks * 16 + (lane & 15);                                      \
            const int bnc = wn * 16 + (lane >> 4) * 4;                                  \
            _Pragma("unroll")                                                           \
            for (int np = 0; np < 2; np++) {                                            \
                unsigned r[4];                                                          \
                ldsm4t(r, smemBase + (BSH_OFF + buf * 2176 + bkr * 68 + bnc + np * 8) * 4); \
                bH[2*np][0] = r[0]; bH[2*np][1] = r[1];                                 \
                bH[2*np+1][0] = r[2]; bH[2*np+1][1] = r[3];                             \
                ldsm4t(r, smemBase + (BSL_OFF + buf * 2176 + bkr * 68 + bnc + np * 8) * 4); \
                bL[2*np][0] = r[0]; bL[2*np][1] = r[1];                                 \
                bL[2*np+1][0] = r[2]; bL[2*np+1][1] = r[3];                             \
            }                                                                           \
            _Pragma("unroll")                                                           \
            for (int mt = 0; mt < 4; mt++)                                              \
                _Pragma("unroll")                                                       \
                for (int nt = 0; nt < 4; nt++) {                                        \
                    mma_bf16(acc[mt][nt], aH[mt], bH[nt]);                              \
                    mma_bf16(acc[mt][nt], aH[mt], bL[nt]);                              \
                    mma_bf16(acc[mt][nt], aL[mt], bH[nt]);                              \
                }                                                                       \
        }                                                                               \
    }                                                                                   \
    __syncthreads();

// ---------------------------------------------------------------------------
// Kernel 1: fused QKV GEMM.  q/k/v ALL written pre-packed bf16 hi/lo.
// ---------------------------------------------------------------------------
__global__ __launch_bounds__(256) void qkv_kernel(
    const float* __restrict__ sinu,
    const float* __restrict__ bq, const float* __restrict__ bk,
    const float* __restrict__ bv)
{
    extern __shared__ unsigned sm[];
    const unsigned smemBase = (unsigned)__cvta_generic_to_shared(sm);

    const int bn  = blockIdx.x * 128;
    const int bm  = blockIdx.y * 128;
    const int mat = bn >> 10;
    const unsigned* __restrict__ WH = mat == 0 ? g_WqH : mat == 1 ? g_WkH : g_WvH;
    const unsigned* __restrict__ WL = mat == 0 ? g_WqL : mat == 1 ? g_WkL : g_WvL;
    const float*    __restrict__ bvec = mat == 0 ? bq : mat == 1 ? bk : bv;
    const int n0w = (bn & (HID_ - 1)) >> 1;

    const int tid  = threadIdx.x;
    const int lane = tid & 31;
    const int g    = lane >> 2;
    const int t    = lane & 3;
    const int wm   = (tid >> 5) >> 2;
    const int wn   = (tid >> 5) & 3;

    float acc[4][4][4];
    #pragma unroll
    for (int i = 0; i < 4; i++)
        #pragma unroll
        for (int j = 0; j < 4; j++)
            #pragma unroll
            for (int e = 0; e < 4; e++) acc[i][j][e] = 0.0f;

    GEMM_MAINLOOP(g_xH, g_xL, WH, WL, n0w)

    unsigned* __restrict__ dH = mat == 0 ? g_qH : mat == 1 ? g_kH : g_vH;
    unsigned* __restrict__ dL = mat == 0 ? g_qL : mat == 1 ? g_kL : g_vL;

    #pragma unroll
    for (int mt = 0; mt < 4; mt++) {
        #pragma unroll
        for (int nt = 0; nt < 4; nt++) {
            const int colg = bn + wn * 32 + nt * 8 + t * 2;
            const int cm   = colg & (HID_ - 1);
            const int hh   = cm >> 6;
            const int d0   = cm & 63;
            #pragma unroll
            for (int half = 0; half < 2; half++) {
                const int row  = bm + wm * 64 + mt * 16 + g + half * 8;
                const int bidx = row >> 11;
                const int s    = row & (S_ - 1);
                float v0 = acc[mt][nt][half * 2 + 0] + bvec[cm];
                float v1 = acc[mt][nt][half * 2 + 1] + bvec[cm + 1];
                if (mat < 2 && d0 < ROT_) {
                    const float sn0 = sinu[(((bidx * 2 + 0) * S_ + s) << 5) + d0];
                    const float cs0 = sinu[(((bidx * 2 + 1) * S_ + s) << 5) + d0];
                    const float sn1 = sinu[(((bidx * 2 + 0) * S_ + s) << 5) + d0 + 1];
                    const float cs1 = sinu[(((bidx * 2 + 1) * S_ + s) << 5) + d0 + 1];
                    v0 *= (cs0 - sn0);
                    v1 *= (cs1 + sn1);
                }
                if (mat == 0) { v0 *= 0.125f * LOG2E; v1 *= 0.125f * LOG2E; }
                const size_t base = ((size_t)bidx * H_ + hh) * S_ + s;
                unsigned hw, lw;
                split2(v0, v1, hw, lw);
                dH[base * 32 + (d0 >> 1)] = hw;
                dL[base * 32 + (d0 >> 1)] = lw;
            }
        }
    }
}

// ---------------------------------------------------------------------------
// Kernel 2: flash attention (round-15 winner, unchanged).
// ---------------------------------------------------------------------------
#define A_KSH 0              // [3][64][36]
#define A_KSL 6912
#define A_VSH 13824          // [3][64][36]
#define A_VSL 20736
#define A_PSH 27648          // [128][36]
#define ATTN_SMEM_BYTES (32256 * 4)   // 129024

#define S_GEMM(dst, bufidx)                                                     \
    _Pragma("unroll")                                                           \
    for (int nt = 0; nt < 8; nt++)                                              \
        _Pragma("unroll")                                                       \
        for (int e = 0; e < 4; e++) dst[nt][e] = 0.0f;                          \
    _Pragma("unroll")                                                           \
    for (int w = 0; w < 4; w++) {                                               \
        _Pragma("unroll")                                                       \
        for (int np = 0; np < 4; np++) {                                        \
            unsigned rH[4], rL[4];                                              \
            const unsigned off = (A_KSH + (bufidx) * 2304 +                     \
                 (np * 16 + kfr) * 36 + w * 8 + kfd) * 4;                       \
            ldsm4(rH, smemBase + off);                                          \
            ldsm4(rL, smemBase + off + (A_KSL - A_KSH) * 4);                    \
            mma_bf16(dst[2*np],   qaH[w], rH);                                  \
            mma_bf16(dst[2*np],   qaH[w], rL);                                  \
            mma_bf16(dst[2*np],   qaL[w], rH);                                  \
            mma_bf16(dst[2*np+1], qaH[w], rH + 2);                              \
            mma_bf16(dst[2*np+1], qaH[w], rL + 2);                              \
            mma_bf16(dst[2*np+1], qaL[w], rH + 2);                              \
        }                                                                       \
    }

#define PV_GEMM(w0, w1, bufidx)                                                 \
    _Pragma("unroll")                                                           \
    for (int w = (w0); w < (w1); w++) {                                         \
        unsigned paH[4];                                                        \
        ldsm4(paH, smemBase + (A_PSH + pfr * 36 + w * 8 + pfc) * 4);            \
        _Pragma("unroll")                                                       \
        for (int np = 0; np < 4; np++) {                                        \
            unsigned rH[4], rL[4];                                              \
            const unsigned off = (A_VSH + (bufidx) * 2304 +                     \
                 (w * 16 + vfr) * 36 + np * 8 + vfc) * 4;                       \
            ldsm4t(rH, smemBase + off);                                         \
            ldsm4t(rL, smemBase + off + (A_VSL - A_VSH) * 4);                   \
            mma_bf16(oacc[2*np],   paH, rH);                                    \
            mma_bf16(oacc[2*np],   paH, rL);                                    \
            mma_bf16(oacc[2*np+1], paH, rH + 2);                                \
            mma_bf16(oacc[2*np+1], paH, rL + 2);                                \
        }                                                                       \
    }

__global__ __launch_bounds__(256) void attn_kernel(const float* __restrict__ bias)
{
    extern __shared__ unsigned sm[];
    const unsigned smemBase = (unsigned)__cvta_generic_to_shared(sm);

    const int bidx = blockIdx.z;
    const int h    = blockIdx.y;
    const int q0   = blockIdx.x * 128;
    const int tid  = threadIdx.x;
    const int lane = tid & 31;
    const int g    = lane >> 2;
    const int t    = lane & 3;
    const int rb   = (tid >> 5) * 16;

    const int has_bias = g_bias_nz;

    const size_t bh = (size_t)bidx * H_ + h;
    const unsigned* __restrict__ qHp = g_qH + (bh * S_ + q0) * 32;
    const unsigned* __restrict__ qLp = g_qL + (bh * S_ + q0) * 32;
    const unsigned* __restrict__ kHp = g_kH + bh * S_ * 32;
    const unsigned* __restrict__ kLp = g_kL + bh * S_ * 32;
    const unsigned* __restrict__ vHp = g_vH + bh * S_ * 32;
    const unsigned* __restrict__ vLp = g_vL + bh * S_ * 32;

    unsigned qaH[4][4], qaL[4][4];
    #pragma unroll
    for (int w = 0; w < 4; w++) {
        qaH[w][0] = qHp[(rb + g)     * 32 + w * 8 + t];
        qaH[w][1] = qHp[(rb + 8 + g) * 32 + w * 8 + t];
        qaH[w][2] = qHp[(rb + g)     * 32 + w * 8 + t + 4];
        qaH[w][3] = qHp[(rb + 8 + g) * 32 + w * 8 + t + 4];
        qaL[w][0] = qLp[(rb + g)     * 32 + w * 8 + t];
        qaL[w][1] = qLp[(rb + 8 + g) * 32 + w * 8 + t];
        qaL[w][2] = qLp[(rb + g)     * 32 + w * 8 + t + 4];
        qaL[w][3] = qLp[(rb + 8 + g) * 32 + w * 8 + t + 4];
    }

    float oacc[8][4];
    #pragma unroll
    for (int i = 0; i < 8; i++)
        #pragma unroll
        for (int e = 0; e < 4; e++) oacc[i][e] = 0.0f;
    float m0 = -1e30f, m1 = -1e30f, l0 = 0.0f, l1 = 0.0f;

    const int krow = tid >> 3, kw4 = (tid & 7) * 4;

    const int kfr = (lane & 7) + ((lane >> 4) & 1) * 8;
    const int kfd = ((lane >> 3) & 1) * 4;
    const int vfr = (lane & 7) + ((lane >> 3) & 1) * 8;
    const int vfc = (lane >> 4) * 4;
    const int pfr = rb + (lane & 15);
    const int pfc = (lane >> 4) * 4;

    #pragma unroll
    for (int s = 0; s < 2; s++) {
        #pragma unroll
        for (int p = 0; p < 2; p++) {
            const int r = krow + p * 32;
            const size_t gr = (size_t)(s * 64 + r) * 32 + kw4;
            cp16(smemBase + (A_KSH + s * 2304 + r * 36 + kw4) * 4, &kHp[gr]);
            cp16(smemBase + (A_KSL + s * 2304 + r * 36 + kw4) * 4, &kLp[gr]);
            cp16(smemBase + (A_VSH + s * 2304 + r * 36 + kw4) * 4, &vHp[gr]);
            cp16(smemBase + (A_VSL + s * 2304 + r * 36 + kw4) * 4, &vLp[gr]);
        }
        CP_COMMIT();
    }
    asm volatile("cp.async.wait_group 1;");
    __syncthreads();

    const size_t brow0 = ((size_t)bidx * S_ + (q0 + rb + g)) * S_;
    const size_t brow1 = brow0 + (size_t)8 * S_;

    float scur[8][4], snxt[8][4];
    S_GEMM(scur, 0)

    int bc = 0;
    for (int c = 0; c < 32; c++) {
        const int bnx = (bc == 2) ? 0 : bc + 1;
        const int bpl = (bnx == 2) ? 0 : bnx + 1;

        asm volatile("cp.async.wait_group 0;");
        __syncthreads();

        if (c + 2 < 32) {
            const int kt2 = (c + 2) * 64;
            #pragma unroll
            for (int p = 0; p < 2; p++) {
                const int r = krow + p * 32;
                const size_t gr = (size_t)(kt2 + r) * 32 + kw4;
                cp16(smemBase + (A_KSH + bpl * 2304 + r * 36 + kw4) * 4, &kHp[gr]);
                cp16(smemBase + (A_KSL + bpl * 2304 + r * 36 + kw4) * 4, &kLp[gr]);
                cp16(smemBase + (A_VSH + bpl * 2304 + r * 36 + kw4) * 4, &vHp[gr]);
                cp16(smemBase + (A_VSL + bpl * 2304 + r * 36 + kw4) * 4, &vLp[gr]);
            }
            CP_COMMIT();
        }

        float2 bb0[8], bb1[8];
        if (has_bias) {
            #pragma unroll
            for (int nt = 0; nt < 8; nt++) {
                bb0[nt] = *(const float2*)&bias[brow0 + c * 64 + nt * 8 + t * 2];
                bb1[nt] = *(const float2*)&bias[brow1 + c * 64 + nt * 8 + t * 2];
            }
        }

        if (c + 1 < 32) {
            S_GEMM(snxt, bnx)
        }

        if (has_bias) {
            #pragma unroll
            for (int nt = 0; nt < 8; nt++) {
                scur[nt][0] += LOG2E * bb0[nt].x; scur[nt][1] += LOG2E * bb0[nt].y;
                scur[nt][2] += LOG2E * bb1[nt].x; scur[nt][3] += LOG2E * bb1[nt].y;
            }
        }

        float mx0 = -1e30f, mx1 = -1e30f;
        #pragma unroll
        for (int nt = 0; nt < 8; nt++) {
            mx0 = fmaxf(mx0, fmaxf(scur[nt][0], scur[nt][1]));
            mx1 = fmaxf(mx1, fmaxf(scur[nt][2], scur[nt][3]));
        }
        mx0 = fmaxf(mx0, __shfl_xor_sync(0xffffffffu, mx0, 1));
        mx0 = fmaxf(mx0, __shfl_xor_sync(0xffffffffu, mx0, 2));
        mx1 = fmaxf(mx1, __shfl_xor_sync(0xffffffffu, mx1, 1));
        mx1 = fmaxf(mx1, __shfl_xor_sync(0xffffffffu, mx1, 2));
        const float mi0 = fmaxf(m0, mx0), mi1 = fmaxf(m1, mx1);
        const float c0 = ex2(m0 - mi0), c1 = ex2(m1 - mi1);
        m0 = mi0; m1 = mi1;
        #pragma unroll
        for (int nt = 0; nt < 8; nt++) {
            oacc[nt][0] *= c0; oacc[nt][1] *= c0;
            oacc[nt][2] *= c1; oacc[nt][3] *= c1;
        }

        float rs0 = 0.0f, rs1 = 0.0f;
        #pragma unroll
        for (int nt = 0; nt < 4; nt++) {
            scur[nt][0] = ex2(scur[nt][0] - mi0);
            scur[nt][1] = ex2(scur[nt][1] - mi0);
            scur[nt][2] = ex2(scur[nt][2] - mi1);
            scur[nt][3] = ex2(scur[nt][3] - mi1);
            rs0 += scur[nt][0] + scur[nt][1];
            rs1 += scur[nt][2] + scur[nt][3];
            sm[A_PSH + (rb + g) * 36 + nt * 4 + t] =
                pack_bf(__float2bfloat16(scur[nt][0]), __float2bfloat16(scur[nt][1]));
            sm[A_PSH + (rb + 8 + g) * 36 + nt * 4 + t] =
                pack_bf(__float2bfloat16(scur[nt][2]), __float2bfloat16(scur[nt][3]));
        }
        __syncwarp();
        PV_GEMM(0, 2, bc)

        #pragma unroll
        for (int nt = 4; nt < 8; nt++) {
            scur[nt][0] = ex2(scur[nt][0] - mi0);
            scur[nt][1] = ex2(scur[nt][1] - mi0);
            scur[nt][2] = ex2(scur[nt][2] - mi1);
            scur[nt][3] = ex2(scur[nt][3] - mi1);
            rs0 += scur[nt][0] + scur[nt][1];
            rs1 += scur[nt][2] + scur[nt][3];
            sm[A_PSH + (rb + g) * 36 + nt * 4 + t] =
                pack_bf(__float2bfloat16(scur[nt][0]), __float2bfloat16(scur[nt][1]));
            sm[A_PSH + (rb + 8 + g) * 36 + nt * 4 + t] =
                pack_bf(__float2bfloat16(scur[nt][2]), __float2bfloat16(scur[nt][3]));
        }
        __syncwarp();
        PV_GEMM(2, 4, bc)

        rs0 += __shfl_xor_sync(0xffffffffu, rs0, 1);
        rs0 += __shfl_xor_sync(0xffffffffu, rs0, 2);
        rs1 += __shfl_xor_sync(0xffffffffu, rs1, 1);
        rs1 += __shfl_xor_sync(0xffffffffu, rs1, 2);
        l0 = l0 * c0 + rs0;
        l1 = l1 * c1 + rs1;

        if (c + 1 < 32) {
            #pragma unroll
            for (int nt = 0; nt < 8; nt++)
                #pragma unroll
                for (int e = 0; e < 4; e++) scur[nt][e] = snxt[nt][e];
        }
        bc = bnx;
    }

    const float inv0 = 1.0f / l0, inv1 = 1.0f / l1;
    #pragma unroll
    for (int nt = 0; nt < 8; nt++) {
        const int col = h * D_ + nt * 8 + t * 2;
        const int r0  = q0 + rb + g;
        unsigned hw, lw;
        split2(oacc[nt][0] * inv0, oacc[nt][1] * inv0, hw, lw);
        g_attnH[((size_t)(bidx * S_ + r0)) * 512 + (col >> 1)] = hw;
        g_attnL[((size_t)(bidx * S_ + r0)) * 512 + (col >> 1)] = lw;
        split2(oacc[nt][2] * inv1, oacc[nt][3] * inv1, hw, lw);
        g_attnH[((size_t)(bidx * S_ + r0 + 8)) * 512 + (col >> 1)] = hw;
        g_attnL[((size_t)(bidx * S_ + r0 + 8)) * 512 + (col >> 1)] = lw;
    }
}

// ---------------------------------------------------------------------------
// Kernel 3: output projection
// ---------------------------------------------------------------------------
__global__ __launch_bounds__(256) void proj_kernel(float* __restrict__ out)
{
    extern __shared__ unsigned sm[];
    const unsigned smemBase = (unsigned)__cvta_generic_to_shared(sm);

    const int bn = blockIdx.x * 128;
    const int bm = blockIdx.y * 128;
    const int n0w = bn >> 1;

    const int tid  = threadIdx.x;
    const int lane = tid & 31;
    const int g    = lane >> 2;
    const int t    = lane & 3;
    const int wm   = (tid >> 5) >> 2;
    const int wn   = (tid >> 5) & 3;

    float acc[4][4][4];
    #pragma unroll
    for (int i = 0; i < 4; i++)
        #pragma unroll
        for (int j = 0; j < 4; j++)
            #pragma unroll
            for (int e = 0; e < 4; e++) acc[i][j][e] = 0.0f;

    GEMM_MAINLOOP(g_attnH, g_attnL, g_WoH, g_WoL, n0w)

    #pragma unroll
    for (int mt = 0; mt < 4; mt++) {
        #pragma unroll
        for (int nt = 0; nt < 4; nt++) {
            const int col = bn + wn * 32 + nt * 8 + t * 2;
            #pragma unroll
            for (int half = 0; half < 2; half++) {
                const int row = bm + wm * 64 + mt * 16 + g + half * 8;
                float2 o = make_float2(acc[mt][nt][half * 2], acc[mt][nt][half * 2 + 1]);
                *(float2*)&out[(size_t)row * HID_ + col] = o;
            }
        }
    }
}

// ---------------------------------------------------------------------------
extern "C" void kernel_launch(void* const* d_in, const int* in_sizes, int n_in,
                              void* d_out, int out_size)
{
    const float* x    = (const float*)d_in[0];
    const float* sinu = (const float*)d_in[1];
    const float* bias = (const float*)d_in[2];
    const float* Wq   = (const float*)d_in[3];
    const float* bq   = (const float*)d_in[4];
    const float* Wk   = (const float*)d_in[5];
    const float* bk   = (const float*)d_in[6];
    const float* Wv   = (const float*)d_in[7];
    const float* bv   = (const float*)d_in[8];
    const float* Wo   = (const float*)d_in[9];
    float* out = (float*)d_out;

    cudaFuncSetAttribute(qkv_kernel,  cudaFuncAttributeMaxDynamicSharedMemorySize, GEMM_SMEM_BYTES);
    cudaFuncSetAttribute(attn_kernel, cudaFuncAttributeMaxDynamicSharedMemorySize, ATTN_SMEM_BYTES);
    cudaFuncSetAttribute(proj_kernel, cudaFuncAttributeMaxDynamicSharedMemorySize, GEMM_SMEM_BYTES);

    prep_all<<<dim3(4096, 1, 5), 256>>>(x, Wq, Wk, Wv, Wo);
    bias_check<<<(size_t)B_ * S_ * S_ / 4 / 256, 256>>>(bias);

    qkv_kernel<<<dim3(24, 32), 256, GEMM_SMEM_BYTES>>>(sinu, bq, bk, bv);
    attn_kernel<<<dim3(S_ / 128, H_, B_), 256, ATTN_SMEM_BYTES>>>(bias);
    proj_kernel<<<dim3(8, 32), 256, GEMM_SMEM_BYTES>>>(out);
}